// round 17
// baseline (speedup 1.0000x reference)
#include <cuda_runtime.h>
#include <math.h>
#include <stdint.h>

#define D_MODEL 768
#define N_HEADS 12
#define D_FF    3072
#define D_KH    64
#define BATCH   2
#define SEQ     2048
#define ROWS    (BATCH * SEQ)
#define OUT_ELEMS ((size_t)ROWS * D_MODEL)
#define NZ (BATCH * N_HEADS)

// Scratch
__device__ float g_q[ROWS * D_MODEL];
__device__ float g_k[ROWS * D_MODEL];
__device__ float g_v[ROWS * D_MODEL];
__device__ float g_ctx[ROWS * D_MODEL];
__device__ float g_t1[ROWS * D_MODEL];
__device__ float g_ao[ROWS * D_MODEL];
__device__ float g_aor[ROWS * D_MODEL];
__device__ float g_ffn[ROWS * D_FF];
__device__ float g_t2[ROWS * D_MODEL];
// tf32-pre-rounded copies
__device__ float g_xr[ROWS * D_MODEL];
__device__ float g_wq[D_MODEL * D_MODEL];
__device__ float g_wk[D_MODEL * D_MODEL];
__device__ float g_wv[D_MODEL * D_MODEL];
__device__ float g_wo[D_MODEL * D_MODEL];
__device__ float g_w1[D_MODEL * D_FF];
__device__ float g_w2[D_FF * D_MODEL];

// ---------------------------------------------------------------------------
// Helpers
// ---------------------------------------------------------------------------
__device__ __forceinline__ uint32_t f2tf32(float f) {
    uint32_t r;
    asm("cvt.rna.tf32.f32 %0, %1;" : "=r"(r) : "f"(f));
    return r;
}
__device__ __forceinline__ float roundtf(float f) { return __uint_as_float(f2tf32(f)); }

__device__ __forceinline__ void mma_tf32(float* c,
                                         uint32_t a0, uint32_t a1, uint32_t a2, uint32_t a3,
                                         uint32_t b0, uint32_t b1) {
    asm("mma.sync.aligned.m16n8k8.row.col.f32.tf32.tf32.f32 "
        "{%0,%1,%2,%3}, {%4,%5,%6,%7}, {%8,%9}, {%0,%1,%2,%3};"
        : "+f"(c[0]), "+f"(c[1]), "+f"(c[2]), "+f"(c[3])
        : "r"(a0), "r"(a1), "r"(a2), "r"(a3), "r"(b0), "r"(b1));
}

__device__ __forceinline__ void ldsm4(uint32_t& r0, uint32_t& r1, uint32_t& r2, uint32_t& r3,
                                      uint32_t a) {
    asm volatile("ldmatrix.sync.aligned.m8n8.x4.shared.b16 {%0,%1,%2,%3}, [%4];"
                 : "=r"(r0), "=r"(r1), "=r"(r2), "=r"(r3) : "r"(a));
}
__device__ __forceinline__ void ldsm2(uint32_t& r0, uint32_t& r1, uint32_t a) {
    asm volatile("ldmatrix.sync.aligned.m8n8.x2.shared.b16 {%0,%1}, [%2];"
                 : "=r"(r0), "=r"(r1) : "r"(a));
}

__device__ __forceinline__ uint32_t smem_u32(const void* p) {
    return (uint32_t)__cvta_generic_to_shared(p);
}

__device__ __forceinline__ void cpa16(uint32_t s, const float* g) {
    asm volatile("cp.async.cg.shared.global [%0], [%1], 16;" :: "r"(s), "l"(g));
}
#define CP_COMMIT() asm volatile("cp.async.commit_group;")
#define CP_WAIT1()  asm volatile("cp.async.wait_group 1;")
#define CP_WAIT0()  asm volatile("cp.async.wait_group 0;")

__device__ __forceinline__ float warp_sum(float v) {
#pragma unroll
    for (int o = 16; o; o >>= 1) v += __shfl_xor_sync(0xffffffffu, v, o);
    return v;
}

// ---------------------------------------------------------------------------
// Pre-round kernel
// ---------------------------------------------------------------------------
struct RoundArgs {
    const float* in[7];
    float* out[7];
    int n[7];
};
__global__ void __launch_bounds__(256)
round7_kernel(RoundArgs a)
{
    int seg = blockIdx.y;
    int base = (blockIdx.x * 256 + threadIdx.x) * 4;
    if (base >= a.n[seg]) return;
    float4 v = *reinterpret_cast<const float4*>(a.in[seg] + base);
    v.x = roundtf(v.x); v.y = roundtf(v.y);
    v.z = roundtf(v.z); v.w = roundtf(v.w);
    *reinterpret_cast<float4*>(a.out[seg] + base) = v;
}

// ---------------------------------------------------------------------------
// cp.async 3-stage pipelined TF32 GEMM, ldmatrix A-frags.
// ---------------------------------------------------------------------------
template <int BM, int BN, int BK, bool RELU, bool ROUND>
__device__ __forceinline__ void gemm_cp_body(const float* __restrict__ A, int lda,
                                             const float* __restrict__ B, int ldb,
                                             float* __restrict__ C, int ldc,
                                             const float* __restrict__ bias, int K,
                                             int row0, int col0)
{
    extern __shared__ float smem[];
    constexpr int A_ST = BK + 4, B_ST = BN + 8;
    constexpr int SA_W = BM * A_ST, SB_W = BK * B_ST;
    constexpr int STAGE_W = SA_W + SB_W;
    constexpr int WTM = BM / 2, WTN = BN / 4;
    constexpr int MT = WTM / 16, NT = WTN / 8;
    constexpr int LA = BM * BK / (256 * 4);
    constexpr int LB = BK * BN / (256 * 4);

    const int tid = threadIdx.x, lane = tid & 31, wid = tid >> 5;
    const int wm = wid & 1, wn = wid >> 1;
    const int g = lane >> 2, t = lane & 3;

    A += (size_t)row0 * lda;
    B += col0;

    const uint32_t sbase = smem_u32(smem);
    const uint32_t aLaneOff = ((wm * WTM + (lane & 15)) * A_ST + (lane >> 4) * 4) * 4;

    int aar[LA], aac[LA], bbr[LB], bbc[LB];
#pragma unroll
    for (int l = 0; l < LA; l++) {
        int idx = tid + l * 256;
        aar[l] = idx / (BK / 4);
        aac[l] = idx % (BK / 4);
    }
#pragma unroll
    for (int l = 0; l < LB; l++) {
        int idx = tid + l * 256;
        bbr[l] = idx / (BN / 4);
        bbc[l] = idx % (BN / 4);
    }

#define ISSUE(kt, st)                                                          \
    {                                                                          \
        uint32_t sa = sbase + (st) * STAGE_W * 4;                              \
        uint32_t sb = sa + SA_W * 4;                                           \
        _Pragma("unroll")                                                      \
        for (int l = 0; l < LA; l++)                                           \
            cpa16(sa + (aar[l] * A_ST + aac[l] * 4) * 4,                       \
                  &A[(size_t)aar[l] * lda + (kt) * BK + aac[l] * 4]);          \
        _Pragma("unroll")                                                      \
        for (int l = 0; l < LB; l++)                                           \
            cpa16(sb + (bbr[l] * B_ST + bbc[l] * 4) * 4,                       \
                  &B[(size_t)((kt) * BK + bbr[l]) * ldb + bbc[l] * 4]);        \
    }

    float c[MT][NT][4] = {};
    const int nk = K / BK;

    ISSUE(0, 0); CP_COMMIT();
    ISSUE(1, 1); CP_COMMIT();

    for (int kt = 0; kt < nk; kt++) {
        CP_WAIT1();
        __syncthreads();
        if (kt + 2 < nk) ISSUE(kt + 2, (kt + 2) % 3);
        CP_COMMIT();

        const uint32_t aStage = sbase + (kt % 3) * STAGE_W * 4 + aLaneOff;
        const uint32_t* pB = reinterpret_cast<const uint32_t*>(smem) + (kt % 3) * STAGE_W + SA_W;
#pragma unroll
        for (int kk = 0; kk < BK / 8; kk++) {
            uint32_t a[MT][4], b[NT][2];
#pragma unroll
            for (int mt = 0; mt < MT; mt++)
                ldsm4(a[mt][0], a[mt][1], a[mt][2], a[mt][3],
                      aStage + (mt * 16 * A_ST + kk * 8) * 4);
#pragma unroll
            for (int nt = 0; nt < NT; nt++) {
                int cc = wn * WTN + nt * 8 + g;
                b[nt][0] = pB[(kk * 8 + t) * B_ST + cc];
                b[nt][1] = pB[(kk * 8 + t + 4) * B_ST + cc];
            }
#pragma unroll
            for (int mt = 0; mt < MT; mt++)
#pragma unroll
                for (int nt = 0; nt < NT; nt++)
                    mma_tf32(c[mt][nt], a[mt][0], a[mt][1], a[mt][2], a[mt][3],
                             b[nt][0], b[nt][1]);
        }
    }
#undef ISSUE

    C += (size_t)row0 * ldc + col0;
#pragma unroll
    for (int mt = 0; mt < MT; mt++) {
        int r = wm * WTM + mt * 16 + g;
#pragma unroll
        for (int nt = 0; nt < NT; nt++) {
            int cc = wn * WTN + nt * 8 + 2 * t;
            float b0 = bias[col0 + cc], b1 = bias[col0 + cc + 1];
            float v00 = c[mt][nt][0] + b0, v01 = c[mt][nt][1] + b1;
            float v10 = c[mt][nt][2] + b0, v11 = c[mt][nt][3] + b1;
            if (RELU) {
                v00 = fmaxf(v00, 0.f); v01 = fmaxf(v01, 0.f);
                v10 = fmaxf(v10, 0.f); v11 = fmaxf(v11, 0.f);
            }
            if (ROUND) {
                v00 = roundtf(v00); v01 = roundtf(v01);
                v10 = roundtf(v10); v11 = roundtf(v11);
            }
            C[(size_t)r * ldc + cc]           = v00;
            C[(size_t)r * ldc + cc + 1]       = v01;
            C[(size_t)(r + 8) * ldc + cc]     = v10;
            C[(size_t)(r + 8) * ldc + cc + 1] = v11;
        }
    }
}

template <int BM, int BN, int BK, bool RELU, bool ROUND>
__global__ void __launch_bounds__(256)
gemm_cp_kernel(const float* __restrict__ A, int lda,
               const float* __restrict__ B, int ldb,
               float* __restrict__ C, int ldc,
               const float* __restrict__ bias, int K)
{
    gemm_cp_body<BM, BN, BK, RELU, ROUND>(A, lda, B, ldb, C, ldc, bias, K,
                                          blockIdx.y * BM, blockIdx.x * BN);
}

__global__ void __launch_bounds__(256)
qkv_cp_kernel(const float* __restrict__ Xr,
              const float* __restrict__ Wq, const float* __restrict__ bq,
              const float* __restrict__ Wk, const float* __restrict__ bk,
              const float* __restrict__ Wv, const float* __restrict__ bv,
              float* __restrict__ q, float* __restrict__ k, float* __restrict__ v)
{
    const float* W; const float* bias; float* C;
    if (blockIdx.z == 0)      { W = Wq; bias = bq; C = q; }
    else if (blockIdx.z == 1) { W = Wk; bias = bk; C = k; }
    else                      { W = Wv; bias = bv; C = v; }
    gemm_cp_body<128, 128, 32, false, true>(Xr, D_MODEL, W, D_MODEL, C, D_MODEL, bias,
                                            D_MODEL, blockIdx.y * 128, blockIdx.x * 128);
}

// ---------------------------------------------------------------------------
// Fused flash attention: one block per (128-row strip, head).
// Pass 1: S=QK/8, e=exp (masked), row sums -> sinv. No gmem writes.
// Pass 2: recompute S, p=e*inv, write p (final attn), accumulate ctx = p@V.
// ---------------------------------------------------------------------------
#define Q_ST 68
#define K_ST 68
#define V_ST 72
#define P_ST 36
#define KW (32 * K_ST)
#define VW (32 * V_ST)
#define ATTN_SMEM_W (128 * Q_ST + 2 * KW + 2 * VW + 128 * P_ST)

__global__ void __launch_bounds__(256)
attn_fused_kernel(const float* __restrict__ q, const float* __restrict__ k,
                  const float* __restrict__ v, const unsigned char* __restrict__ mask,
                  float* __restrict__ attn, float* __restrict__ ctx)
{
    extern __shared__ float sm[];
    float* Qs  = sm;                          // [128][Q_ST]
    float* Ksb = sm + 128 * Q_ST;             // [2][32][K_ST]
    float* Vsb = Ksb + 2 * KW;                // [2][32][V_ST]
    float* pAs = Vsb + 2 * VW;                // [128][P_ST]
    __shared__ float sred[4][128];
    __shared__ float sinv[128];

    const int strip = blockIdx.x, z = blockIdx.y;
    const int b = z / N_HEADS, h = z % N_HEADS;
    const int tid = threadIdx.x, lane = tid & 31, wid = tid >> 5;
    const int wm = wid & 1, wn = wid >> 1;
    const int g = lane >> 2, t = lane & 3;

    const float* Qp = q + (size_t)b * SEQ * D_MODEL + h * D_KH + (size_t)strip * 128 * D_MODEL;
    const float* Kp = k + (size_t)b * SEQ * D_MODEL + h * D_KH;
    const float* Vp = v + (size_t)b * SEQ * D_MODEL + h * D_KH;
    float* Ap = attn + (size_t)z * SEQ * SEQ + (size_t)strip * 128 * SEQ;
    const unsigned char* Mp = mask + (size_t)b * SEQ * SEQ + (size_t)strip * 128 * SEQ;
    float* Cp = ctx + (size_t)b * SEQ * D_MODEL + h * D_KH + (size_t)strip * 128 * D_MODEL;

#pragma unroll
    for (int l = 0; l < 8; l++) {
        int idx = tid + l * 256;
        int r = idx >> 4, c4 = idx & 15;
        *reinterpret_cast<float4*>(&Qs[r * Q_ST + c4 * 4]) =
            *reinterpret_cast<const float4*>(&Qp[(size_t)r * D_MODEL + c4 * 4]);
    }

    const uint32_t ksmB = smem_u32(Ksb);
    const uint32_t vsmB = smem_u32(Vsb);
    const uint32_t aQ = smem_u32(Qs) + ((wm * 64 + (lane & 15)) * Q_ST + (lane >> 4) * 4) * 4;
    const uint32_t bKoff = ((wn * 8 + (lane & 7)) * K_ST + ((lane >> 3) & 1) * 4) * 4;
    const uint32_t aP = smem_u32(pAs) + ((wm * 64 + (lane & 15)) * P_ST + (lane >> 4) * 4) * 4;

#define ISSUE_K(kt, buf)                                                        \
    { _Pragma("unroll")                                                         \
      for (int l = 0; l < 2; l++) {                                             \
          int idx = tid + l * 256; int rr = idx >> 4, c4 = idx & 15;            \
          cpa16(ksmB + ((buf) * KW + rr * K_ST + c4 * 4) * 4,                   \
                &Kp[(size_t)((kt) * 32 + rr) * D_MODEL + c4 * 4]); } }
#define ISSUE_V(kt, buf)                                                        \
    { _Pragma("unroll")                                                         \
      for (int l = 0; l < 2; l++) {                                             \
          int idx = tid + l * 256; int rr = idx >> 4, c4 = idx & 15;            \
          cpa16(vsmB + ((buf) * VW + rr * V_ST + c4 * 4) * 4,                   \
                &Vp[(size_t)((kt) * 32 + rr) * D_MODEL + c4 * 4]); } }

#define S_COMPUTE(kb, c)                                                        \
    { _Pragma("unroll")                                                         \
      for (int kk = 0; kk < 8; kk++) {                                          \
          uint32_t a[4][4]; uint32_t b0, b1;                                    \
          _Pragma("unroll")                                                     \
          for (int mt = 0; mt < 4; mt++)                                        \
              ldsm4(a[mt][0], a[mt][1], a[mt][2], a[mt][3],                     \
                    aQ + (mt * 16 * Q_ST + kk * 8) * 4);                        \
          ldsm2(b0, b1, (kb) + kk * 8 * 4);                                     \
          _Pragma("unroll")                                                     \
          for (int mt = 0; mt < 4; mt++)                                        \
              mma_tf32(c[mt], a[mt][0], a[mt][1], a[mt][2], a[mt][3], b0, b1);  \
      } }

    // ---------------- Pass 1: row sums ----------------
    float rs[4][2];
#pragma unroll
    for (int mt = 0; mt < 4; mt++) { rs[mt][0] = 0.f; rs[mt][1] = 0.f; }

    ISSUE_K(0, 0); CP_COMMIT();
    for (int kt = 0; kt < 64; kt++) {
        if (kt + 1 < 64) ISSUE_K(kt + 1, (kt + 1) & 1);
        CP_COMMIT();
        CP_WAIT1();
        __syncthreads();

        float c[4][4] = {};
        const uint32_t kb = ksmB + (kt & 1) * KW * 4 + bKoff;
        S_COMPUTE(kb, c);

        const int cb = kt * 32 + wn * 8 + 2 * t;
#pragma unroll
        for (int mt = 0; mt < 4; mt++) {
            int r = wm * 64 + mt * 16 + g;
            float e00 = Mp[(size_t)r * SEQ + cb]           ? 0.f : __expf(c[mt][0] * 0.125f);
            float e01 = Mp[(size_t)r * SEQ + cb + 1]       ? 0.f : __expf(c[mt][1] * 0.125f);
            float e10 = Mp[(size_t)(r + 8) * SEQ + cb]     ? 0.f : __expf(c[mt][2] * 0.125f);
            float e11 = Mp[(size_t)(r + 8) * SEQ + cb + 1] ? 0.f : __expf(c[mt][3] * 0.125f);
            rs[mt][0] += e00 + e01;
            rs[mt][1] += e10 + e11;
        }
        __syncthreads();
    }
    CP_WAIT0();

#pragma unroll
    for (int mt = 0; mt < 4; mt++) {
#pragma unroll
        for (int hh = 0; hh < 2; hh++) {
            rs[mt][hh] += __shfl_xor_sync(0xffffffffu, rs[mt][hh], 1);
            rs[mt][hh] += __shfl_xor_sync(0xffffffffu, rs[mt][hh], 2);
        }
    }
    if (t == 0) {
#pragma unroll
        for (int mt = 0; mt < 4; mt++) {
            int r = wm * 64 + mt * 16 + g;
            sred[wn][r]     = rs[mt][0];
            sred[wn][r + 8] = rs[mt][1];
        }
    }
    __syncthreads();
    if (tid < 128)
        sinv[tid] = 1.0f / (sred[0][tid] + sred[1][tid] + sred[2][tid] + sred[3][tid]);
    __syncthreads();

    float inv0[4], inv1[4];
#pragma unroll
    for (int mt = 0; mt < 4; mt++) {
        inv0[mt] = sinv[wm * 64 + mt * 16 + g];
        inv1[mt] = sinv[wm * 64 + mt * 16 + g + 8];
    }

    // ---------------- Pass 2: write p, accumulate ctx ----------------
    float c2[4][2][4] = {};

    ISSUE_K(0, 0); ISSUE_V(0, 0); CP_COMMIT();
    for (int kt = 0; kt < 64; kt++) {
        if (kt + 1 < 64) { ISSUE_K(kt + 1, (kt + 1) & 1); ISSUE_V(kt + 1, (kt + 1) & 1); }
        CP_COMMIT();
        CP_WAIT1();
        __syncthreads();

        float c[4][4] = {};
        const uint32_t kb = ksmB + (kt & 1) * KW * 4 + bKoff;
        S_COMPUTE(kb, c);

        const int cb = kt * 32 + wn * 8 + 2 * t;
        const int cl = wn * 8 + 2 * t;
#pragma unroll
        for (int mt = 0; mt < 4; mt++) {
            int r = wm * 64 + mt * 16 + g;
            float p00 = Mp[(size_t)r * SEQ + cb]           ? 0.f : __expf(c[mt][0] * 0.125f) * inv0[mt];
            float p01 = Mp[(size_t)r * SEQ + cb + 1]       ? 0.f : __expf(c[mt][1] * 0.125f) * inv0[mt];
            float p10 = Mp[(size_t)(r + 8) * SEQ + cb]     ? 0.f : __expf(c[mt][2] * 0.125f) * inv1[mt];
            float p11 = Mp[(size_t)(r + 8) * SEQ + cb + 1] ? 0.f : __expf(c[mt][3] * 0.125f) * inv1[mt];
            Ap[(size_t)r * SEQ + cb]           = p00;
            Ap[(size_t)r * SEQ + cb + 1]       = p01;
            Ap[(size_t)(r + 8) * SEQ + cb]     = p10;
            Ap[(size_t)(r + 8) * SEQ + cb + 1] = p11;
            pAs[r * P_ST + cl]           = __uint_as_float(f2tf32(p00));
            pAs[r * P_ST + cl + 1]       = __uint_as_float(f2tf32(p01));
            pAs[(r + 8) * P_ST + cl]     = __uint_as_float(f2tf32(p10));
            pAs[(r + 8) * P_ST + cl + 1] = __uint_as_float(f2tf32(p11));
        }
        __syncthreads();

        const uint32_t* Vsu = reinterpret_cast<const uint32_t*>(Vsb + (kt & 1) * VW);
#pragma unroll
        for (int kk2 = 0; kk2 < 4; kk2++) {
            uint32_t a[4][4], bb[2][2];
#pragma unroll
            for (int mt = 0; mt < 4; mt++)
                ldsm4(a[mt][0], a[mt][1], a[mt][2], a[mt][3],
                      aP + (mt * 16 * P_ST + kk2 * 8) * 4);
#pragma unroll
            for (int nt = 0; nt < 2; nt++) {
                int cc = wn * 16 + nt * 8 + g;
                bb[nt][0] = Vsu[(kk2 * 8 + t) * V_ST + cc];
                bb[nt][1] = Vsu[(kk2 * 8 + t + 4) * V_ST + cc];
            }
#pragma unroll
            for (int mt = 0; mt < 4; mt++)
#pragma unroll
                for (int nt = 0; nt < 2; nt++)
                    mma_tf32(c2[mt][nt], a[mt][0], a[mt][1], a[mt][2], a[mt][3],
                             bb[nt][0], bb[nt][1]);
        }
        __syncthreads();
    }
    CP_WAIT0();

#pragma unroll
    for (int mt = 0; mt < 4; mt++) {
        int r = wm * 64 + mt * 16 + g;
#pragma unroll
        for (int nt = 0; nt < 2; nt++) {
            int cc = wn * 16 + nt * 8 + 2 * t;
            Cp[(size_t)r * D_MODEL + cc]           = roundtf(c2[mt][nt][0]);
            Cp[(size_t)r * D_MODEL + cc + 1]       = roundtf(c2[mt][nt][1]);
            Cp[(size_t)(r + 8) * D_MODEL + cc]     = roundtf(c2[mt][nt][2]);
            Cp[(size_t)(r + 8) * D_MODEL + cc + 1] = roundtf(c2[mt][nt][3]);
        }
    }
}

// ---------------------------------------------------------------------------
// LayerNorm
// ---------------------------------------------------------------------------
__global__ void __launch_bounds__(256)
ln_kernel(const float* __restrict__ x, const float* __restrict__ resid,
          const float* __restrict__ gamma, const float* __restrict__ beta,
          float* __restrict__ out, float* __restrict__ out_r)
{
    __shared__ float s_s[8];
    __shared__ float s_ss[8];
    const int row = blockIdx.x;
    const int tid = threadIdx.x;
    const int lane = tid & 31;
    const int wid = tid >> 5;
    const float* xr = x + (size_t)row * D_MODEL;
    const float* rr = resid + (size_t)row * D_MODEL;

    float v[3];
    float s = 0.f, ss = 0.f;
#pragma unroll
    for (int i = 0; i < 3; i++) {
        int c = tid + i * 256;
        v[i] = xr[c] + rr[c];
        s  += v[i];
        ss += v[i] * v[i];
    }
    s = warp_sum(s);
    ss = warp_sum(ss);
    if (lane == 0) { s_s[wid] = s; s_ss[wid] = ss; }
    __syncthreads();
    float ts = 0.f, tss = 0.f;
#pragma unroll
    for (int i = 0; i < 8; i++) { ts += s_s[i]; tss += s_ss[i]; }
    const float mean = ts * (1.0f / D_MODEL);
    const float var  = tss * (1.0f / D_MODEL) - mean * mean;
    const float inv  = rsqrtf(var + 1e-5f);

#pragma unroll
    for (int i = 0; i < 3; i++) {
        int c = tid + i * 256;
        float o = (v[i] - mean) * inv * gamma[c] + beta[c];
        out[(size_t)row * D_MODEL + c] = o;
        if (out_r) out_r[(size_t)row * D_MODEL + c] = roundtf(o);
    }
}

// ---------------------------------------------------------------------------
// Launch
// ---------------------------------------------------------------------------
extern "C" void kernel_launch(void* const* d_in, const int* in_sizes, int n_in,
                              void* d_out, int out_size)
{
    const float* X              = (const float*)d_in[0];
    const unsigned char* mask   = (const unsigned char*)d_in[1];
    const float* Wq = (const float*)d_in[2];
    const float* bq = (const float*)d_in[3];
    const float* Wk = (const float*)d_in[4];
    const float* bk = (const float*)d_in[5];
    const float* Wv = (const float*)d_in[6];
    const float* bv = (const float*)d_in[7];
    const float* Wo = (const float*)d_in[8];
    const float* bo = (const float*)d_in[9];
    const float* ln1g = (const float*)d_in[10];
    const float* ln1b = (const float*)d_in[11];
    const float* W1 = (const float*)d_in[12];
    const float* b1 = (const float*)d_in[13];
    const float* W2 = (const float*)d_in[14];
    const float* b2 = (const float*)d_in[15];
    const float* ln2g = (const float*)d_in[16];
    const float* ln2b = (const float*)d_in[17];

    float* out  = (float*)d_out;
    float* attn = out + OUT_ELEMS;

    float *q, *k, *v, *ctx, *t1, *ao, *aor, *ffn, *t2;
    float *xr, *wq, *wk, *wv, *wo, *w1, *w2;
    cudaGetSymbolAddress((void**)&q,   g_q);
    cudaGetSymbolAddress((void**)&k,   g_k);
    cudaGetSymbolAddress((void**)&v,   g_v);
    cudaGetSymbolAddress((void**)&ctx, g_ctx);
    cudaGetSymbolAddress((void**)&t1,  g_t1);
    cudaGetSymbolAddress((void**)&ao,  g_ao);
    cudaGetSymbolAddress((void**)&aor, g_aor);
    cudaGetSymbolAddress((void**)&ffn, g_ffn);
    cudaGetSymbolAddress((void**)&t2,  g_t2);
    cudaGetSymbolAddress((void**)&xr,  g_xr);
    cudaGetSymbolAddress((void**)&wq,  g_wq);
    cudaGetSymbolAddress((void**)&wk,  g_wk);
    cudaGetSymbolAddress((void**)&wv,  g_wv);
    cudaGetSymbolAddress((void**)&wo,  g_wo);
    cudaGetSymbolAddress((void**)&w1,  g_w1);
    cudaGetSymbolAddress((void**)&w2,  g_w2);

    RoundArgs ra;
    ra.in[0] = X;  ra.out[0] = xr; ra.n[0] = ROWS * D_MODEL;
    ra.in[1] = Wq; ra.out[1] = wq; ra.n[1] = D_MODEL * D_MODEL;
    ra.in[2] = Wk; ra.out[2] = wk; ra.n[2] = D_MODEL * D_MODEL;
    ra.in[3] = Wv; ra.out[3] = wv; ra.n[3] = D_MODEL * D_MODEL;
    ra.in[4] = Wo; ra.out[4] = wo; ra.n[4] = D_MODEL * D_MODEL;
    ra.in[5] = W1; ra.out[5] = w1; ra.n[5] = D_MODEL * D_FF;
    ra.in[6] = W2; ra.out[6] = w2; ra.n[6] = D_FF * D_MODEL;
    round7_kernel<<<dim3((ROWS * D_MODEL) / 1024, 7), 256>>>(ra);

    const int smem_gemm128 = 3 * (128 * 36 + 32 * 136) * 4;   // 107520
    const int smem_gemm64  = 3 * (128 * 36 + 32 * 72)  * 4;   // 82944
    const int smem_attn    = ATTN_SMEM_W * 4;                 // 89088

    cudaFuncSetAttribute(gemm_cp_kernel<128, 128, 32, true, true>,
                         cudaFuncAttributeMaxDynamicSharedMemorySize, smem_gemm128);
    cudaFuncSetAttribute(gemm_cp_kernel<128, 64, 32, false, false>,
                         cudaFuncAttributeMaxDynamicSharedMemorySize, smem_gemm64);
    cudaFuncSetAttribute(qkv_cp_kernel,
                         cudaFuncAttributeMaxDynamicSharedMemorySize, smem_gemm128);
    cudaFuncSetAttribute(attn_fused_kernel,
                         cudaFuncAttributeMaxDynamicSharedMemorySize, smem_attn);

    qkv_cp_kernel<<<dim3(D_MODEL / 128, ROWS / 128, 3), 256, smem_gemm128>>>(
        xr, wq, bq, wk, bk, wv, bv, q, k, v);

    attn_fused_kernel<<<dim3(SEQ / 128, NZ), 256, smem_attn>>>(
        q, k, v, mask, attn, ctx);

    gemm_cp_kernel<128, 64, 32, false, false><<<dim3(D_MODEL / 64, ROWS / 128), 256, smem_gemm64>>>(
        ctx, D_MODEL, wo, D_MODEL, t1, D_MODEL, bo, D_MODEL);
    ln_kernel<<<ROWS, 256>>>(t1, X, ln1g, ln1b, ao, aor);

    gemm_cp_kernel<128, 128, 32, true, true><<<dim3(D_FF / 128, ROWS / 128), 256, smem_gemm128>>>(
        aor, D_MODEL, w1, D_FF, ffn, D_FF, b1, D_MODEL);
    gemm_cp_kernel<128, 64, 32, false, false><<<dim3(D_MODEL / 64, ROWS / 128), 256, smem_gemm64>>>(
        ffn, D_FF, w2, D_MODEL, t2, D_MODEL, b2, D_FF);

    ln_kernel<<<ROWS, 256>>>(t2, ao, ln2g, ln2b, out, nullptr);
}